// round 14
// baseline (speedup 1.0000x reference)
#include <cuda_runtime.h>
#include <cuda_fp16.h>
#include <cstdint>

// ---------------------------------------------------------------------------
// Problem constants
// ---------------------------------------------------------------------------
#define BATCH   4
#define NSEQ    2048
#define DIM     1024
#define HEADS   16
#define HDIM    64
#define M_ROWS  8192
#define N_COLS  3072
#define K_DIM   1024
#define SCALE   32.0f

// qkv GEMM tiling (round-6 proven: CTA 128x128, 8 warps 4x2, 3 stages, 2 CTAs/SM)
#define QBM 128
#define QBN 128
#define KCH 64
#define NCHUNK (K_DIM / KCH)
#define STAGE_BYTES 32768
#define NSTAGE 3
#define SMEM_DYN (NSTAGE * STAGE_BYTES)

// kv_partial pipeline (round-12): 8 splits x 256 rows; 8 subtiles, 3 stages
#define KVP_STAGE 8192
#define KVP_SMEM (3 * KVP_STAGE)     // 24576

#define OUT_SMEM 32768               // q 16KB + KVT hi 8KB + KVT lo 8KB

// ---------------------------------------------------------------------------
// Scratch (device globals — allocation-free per harness rules)
// ---------------------------------------------------------------------------
__device__ __align__(16) __half g_Ah[(size_t)M_ROWS * K_DIM];      // fp16(x)
__device__ __align__(16) __half g_Bh[(size_t)N_COLS * K_DIM];      // W^T permuted fp16
__device__ float g_biasP[N_COLS];
// Y fp16, permuted: [row][t*1024 + h*64 + d]
__device__ __align__(16) __half g_Y16[(size_t)M_ROWS * N_COLS];
__device__ float g_KVp[64 * 8 * HDIM * HDIM];                      // KV^T partials [d2][d1]
__device__ __align__(16) __half g_KVThi[64 * HDIM * HDIM];
__device__ __align__(16) __half g_KVTlo[64 * HDIM * HDIM];

// ---------------------------------------------------------------------------
// Inline PTX (valid on base sm_103 target)
// ---------------------------------------------------------------------------
__device__ __forceinline__ uint32_t smem_u32(const void* p) {
    uint32_t a;
    asm("{ .reg .u64 t; cvta.to.shared.u64 t, %1; cvt.u32.u64 %0, t; }" : "=r"(a) : "l"(p));
    return a;
}
__device__ __forceinline__ void cp16(uint32_t dst, const void* src) {
    asm volatile("cp.async.cg.shared.global [%0], [%1], 16;" :: "r"(dst), "l"(src));
}
__device__ __forceinline__ void ldsm4(uint32_t* r, uint32_t addr) {
    asm volatile("ldmatrix.sync.aligned.m8n8.x4.shared.b16 {%0,%1,%2,%3}, [%4];"
        : "=r"(r[0]), "=r"(r[1]), "=r"(r[2]), "=r"(r[3]) : "r"(addr));
}
__device__ __forceinline__ void ldsm4t(uint32_t* r, uint32_t addr) {
    asm volatile("ldmatrix.sync.aligned.m8n8.x4.trans.shared.b16 {%0,%1,%2,%3}, [%4];"
        : "=r"(r[0]), "=r"(r[1]), "=r"(r[2]), "=r"(r[3]) : "r"(addr));
}
__device__ __forceinline__ void hmma(float* d, const uint32_t* a, const uint32_t* b) {
    asm volatile("mma.sync.aligned.m16n8k16.row.col.f32.f16.f16.f32 "
        "{%0,%1,%2,%3}, {%4,%5,%6,%7}, {%8,%9}, {%0,%1,%2,%3};"
        : "+f"(d[0]), "+f"(d[1]), "+f"(d[2]), "+f"(d[3])
        : "r"(a[0]), "r"(a[1]), "r"(a[2]), "r"(a[3]), "r"(b[0]), "r"(b[1]));
}

// ---------------------------------------------------------------------------
// conv_x: fp32 x -> fp16 (triggers early so conv_w overlaps)
// ---------------------------------------------------------------------------
__global__ __launch_bounds__(256)
void conv_x(const float4* __restrict__ x)
{
    cudaTriggerProgrammaticLaunchCompletion();
    size_t i = (size_t)blockIdx.x * 256 + threadIdx.x;
    float4 v = x[i];
    __half h[4];
    h[0] = __float2half(v.x); h[1] = __float2half(v.y);
    h[2] = __float2half(v.z); h[3] = __float2half(v.w);
    *(uint2*)(g_Ah + 4 * i) = *(uint2*)h;
}

// ---------------------------------------------------------------------------
// conv_w: independent of conv_x — PDL launch, NO grid sync -> true overlap
// W [k][c] -> g_Bh[c'][k];  c = h*192+d*3+t  ->  c' = t*1024+h*64+d
// ---------------------------------------------------------------------------
__global__ __launch_bounds__(256)
void conv_w(const float* __restrict__ W, const float* __restrict__ bias)
{
    cudaTriggerProgrammaticLaunchCompletion();
    __shared__ float tile[32][193];
    const int h  = blockIdx.x;
    const int k0 = blockIdx.y * 32;
    const int tid = threadIdx.x;

    if (blockIdx.y == 0 && tid < 192) {
        int d = tid & 63, t = tid >> 6;
        g_biasP[t * 1024 + h * 64 + d] = bias[h * 192 + d * 3 + t];
    }

    for (int e = tid; e < 32 * 192; e += 256) {
        int r = e / 192, cc = e % 192;
        tile[r][cc] = W[(size_t)(k0 + r) * N_COLS + h * 192 + cc];
    }
    __syncthreads();

    for (int e = tid; e < 3 * 64 * 32; e += 256) {
        int t = e >> 11;
        int rem = e & 2047;
        int d = rem >> 5, kk = rem & 31;
        float v = tile[kk][d * 3 + t];
        g_Bh[(size_t)(t * 1024 + h * 64 + d) * K_DIM + k0 + kk] = __float2half(v);
    }
}

// ---------------------------------------------------------------------------
// Kernel A: Y16 = fp16(X @ W' + bias') via mma.sync fp16 (round-6 exact body)
// grid (24, 64), 256 threads (8 warps, 4x2), 2 CTAs/SM
// ---------------------------------------------------------------------------
__device__ __forceinline__ void load_chunk(uint32_t stage_sb, int rowBase, int colBase,
                                           int k0, int tid)
{
#pragma unroll
    for (int i = 0; i < 4; i++) {
        int o = tid + i * 256;
        int r = o >> 3, ch = o & 7;
        cp16(stage_sb + r * 128 + ((ch ^ (r & 7)) << 4),
             g_Ah + (size_t)(rowBase + r) * K_DIM + k0 + ch * 8);
    }
#pragma unroll
    for (int i = 0; i < 4; i++) {
        int o = tid + i * 256;
        int r = o >> 3, ch = o & 7;
        cp16(stage_sb + 16384 + r * 128 + ((ch ^ (r & 7)) << 4),
             g_Bh + (size_t)(colBase + r) * K_DIM + k0 + ch * 8);
    }
}

__global__ __launch_bounds__(256, 2)
void qkv_mma()
{
    cudaTriggerProgrammaticLaunchCompletion();
    cudaGridDependencySynchronize();          // wait: g_Ah, g_Bh, g_biasP

    extern __shared__ char smem[];
    const uint32_t sb = smem_u32(smem);
    const int tid = threadIdx.x;
    const int wid = tid >> 5, lid = tid & 31;
    const int warp_m = wid >> 1, warp_n = wid & 1;
    const int rowBase = blockIdx.y * QBM;
    const int colBase = blockIdx.x * QBN;

    float acc[2][8][4];
#pragma unroll
    for (int mt = 0; mt < 2; mt++)
#pragma unroll
        for (int nt = 0; nt < 8; nt++)
#pragma unroll
            for (int j = 0; j < 4; j++) acc[mt][nt][j] = 0.0f;

#pragma unroll
    for (int c = 0; c < NSTAGE; c++) {
        load_chunk(sb + c * STAGE_BYTES, rowBase, colBase, c * KCH, tid);
        asm volatile("cp.async.commit_group;" ::: "memory");
    }

    const uint32_t aRowOff = (uint32_t)(warp_m * 32 + (lid & 15)) * 128;
    const uint32_t bRowOff = (uint32_t)(warp_n * 64 + (lid & 7) + ((lid >> 4) & 1) * 8) * 128;
    const int xorC   = lid & 7;
    const int chSelA = lid >> 4;
    const int chSelB = (lid >> 3) & 1;

    for (int c = 0; c < NCHUNK; c++) {
        asm volatile("cp.async.wait_group 2;" ::: "memory");
        __syncthreads();
        const uint32_t st = sb + (uint32_t)(c % NSTAGE) * STAGE_BYTES;

#pragma unroll
        for (int ks = 0; ks < 4; ks++) {
            const uint32_t chA = (uint32_t)((ks * 2 + chSelA) ^ xorC) << 4;
            const uint32_t chB = (uint32_t)((ks * 2 + chSelB) ^ xorC) << 4;
            uint32_t ah[2][4];
#pragma unroll
            for (int mt = 0; mt < 2; mt++)
                ldsm4(ah[mt], st + aRowOff + mt * (16 * 128) + chA);
            uint32_t bh[4][4];
#pragma unroll
            for (int p = 0; p < 4; p++)
                ldsm4(bh[p], st + 16384 + bRowOff + p * (16 * 128) + chB);
#pragma unroll
            for (int mt = 0; mt < 2; mt++)
#pragma unroll
                for (int p = 0; p < 4; p++) {
                    hmma(acc[mt][2 * p + 0], ah[mt], &bh[p][0]);
                    hmma(acc[mt][2 * p + 1], ah[mt], &bh[p][2]);
                }
        }
        __syncthreads();
        if (c + NSTAGE < NCHUNK)
            load_chunk(st, rowBase, colBase, (c + NSTAGE) * KCH, tid);
        asm volatile("cp.async.commit_group;" ::: "memory");
    }

    // Epilogue: + bias -> fp16 Y
    const int er = rowBase + warp_m * 32 + (lid >> 2);
    const int ec = colBase + warp_n * 64 + (lid & 3) * 2;
    float2 bb[8];
#pragma unroll
    for (int nt = 0; nt < 8; nt++) bb[nt] = *(const float2*)&g_biasP[ec + nt * 8];
#pragma unroll
    for (int mt = 0; mt < 2; mt++) {
        const int r0 = er + mt * 16;
#pragma unroll
        for (int nt = 0; nt < 8; nt++) {
            __half2 v0 = __floats2half2_rn(acc[mt][nt][0] + bb[nt].x,
                                           acc[mt][nt][1] + bb[nt].y);
            __half2 v1 = __floats2half2_rn(acc[mt][nt][2] + bb[nt].x,
                                           acc[mt][nt][3] + bb[nt].y);
            *(__half2*)&g_Y16[(size_t)r0 * N_COLS + ec + nt * 8] = v0;
            *(__half2*)&g_Y16[(size_t)(r0 + 8) * N_COLS + ec + nt * 8] = v1;
        }
    }
}

// ---------------------------------------------------------------------------
// Kernel B: KV^T partials via HMMA, 3-stage pipelined 32-row subtiles
// grid (64, 8), 128 threads, 24KB smem (round-12 exact body)
// ---------------------------------------------------------------------------
__device__ __forceinline__ void kvp_load_sub(uint32_t stg, size_t rowBase, int s,
                                             int vCol, int kCol, int tid)
{
#pragma unroll
    for (int i = 0; i < 4; i++) {
        int o = tid + i * 128;
        int t = o >> 8;
        int r = (o >> 3) & 31;
        int ch = o & 7;
        uint32_t sw = stg + t * 4096 + r * 128 + ((ch ^ (r & 7)) << 4);
        cp16(sw, g_Y16 + (rowBase + s * 32 + r) * N_COLS
                  + (t ? kCol : vCol) + ch * 8);
    }
}

__global__ __launch_bounds__(128)
void kv_partial()
{
    cudaTriggerProgrammaticLaunchCompletion();
    cudaGridDependencySynchronize();          // wait: g_Y16

    extern __shared__ char smc[];
    const uint32_t sbase = smem_u32(smc);
    const int pair  = blockIdx.x;
    const int split = blockIdx.y;
    const int b = pair >> 4, h = pair & 15;
    const int tid = threadIdx.x;
    const int wid = tid >> 5, lid = tid & 31;

    const size_t rowBase = (size_t)b * NSEQ + (size_t)split * 256;
    const int kCol = 1024 + h * HDIM;
    const int vCol = 2048 + h * HDIM;

    kvp_load_sub(sbase,             rowBase, 0, vCol, kCol, tid);
    asm volatile("cp.async.commit_group;" ::: "memory");
    kvp_load_sub(sbase + KVP_STAGE, rowBase, 1, vCol, kCol, tid);
    asm volatile("cp.async.commit_group;" ::: "memory");

    float acc[4][2][4];
#pragma unroll
    for (int mt = 0; mt < 4; mt++)
#pragma unroll
        for (int bn = 0; bn < 2; bn++)
#pragma unroll
            for (int j = 0; j < 4; j++) acc[mt][bn][j] = 0.0f;

    const int krA = (lid & 7) | ((lid & 16) >> 1);
    const int mSel = (lid >> 3) & 1;
    const int krB = lid & 15;
    const int nSel = lid >> 4;
    const int xA = krA & 7;
    const int xB = krB & 7;

    for (int s = 0; s < 8; s++) {
        if (s < 7) { asm volatile("cp.async.wait_group 1;" ::: "memory"); }
        else       { asm volatile("cp.async.wait_group 0;" ::: "memory"); }
        __syncthreads();

        if (s + 2 < 8) {
            kvp_load_sub(sbase + (uint32_t)((s + 2) % 3) * KVP_STAGE,
                         rowBase, s + 2, vCol, kCol, tid);
            asm volatile("cp.async.commit_group;" ::: "memory");
        }

        const uint32_t stV = sbase + (uint32_t)(s % 3) * KVP_STAGE;
        const uint32_t stK = stV + 4096;
#pragma unroll
        for (int kl = 0; kl < 2; kl++) {
            const int rowA = kl * 16 + krA;
            const int rowB = kl * 16 + krB;
            uint32_t a[4][4];
#pragma unroll
            for (int mt = 0; mt < 4; mt++) {
                uint32_t ch = (uint32_t)((mt * 2 + mSel) ^ xA) << 4;
                ldsm4t(a[mt], stV + rowA * 128 + ch);
            }
            uint32_t bf[4];
            {
                uint32_t ch = (uint32_t)((wid * 2 + nSel) ^ xB) << 4;
                ldsm4t(bf, stK + rowB * 128 + ch);
            }
#pragma unroll
            for (int mt = 0; mt < 4; mt++) {
                hmma(acc[mt][0], a[mt], &bf[0]);
                hmma(acc[mt][1], a[mt], &bf[2]);
            }
        }
    }

    float* dst = g_KVp + ((size_t)pair * 8 + split) * (HDIM * HDIM);
    const int d1c = wid * 16 + (lid & 3) * 2;
#pragma unroll
    for (int mt = 0; mt < 4; mt++) {
        const int d2r = mt * 16 + (lid >> 2);
#pragma unroll
        for (int bn = 0; bn < 2; bn++) {
            *(float2*)&dst[(size_t)d2r * HDIM + d1c + bn * 8] =
                *(float2*)&acc[mt][bn][0];
            *(float2*)&dst[(size_t)(d2r + 8) * HDIM + d1c + bn * 8] =
                *(float2*)&acc[mt][bn][2];
        }
    }
}

// ---------------------------------------------------------------------------
// kv_reduce: float4-vectorized; sum 8 splits, scale, emit fp16 hi+lo
// ---------------------------------------------------------------------------
__global__ __launch_bounds__(256)
void kv_reduce()
{
    cudaTriggerProgrammaticLaunchCompletion();
    cudaGridDependencySynchronize();          // wait: g_KVp

    int idx = blockIdx.x * 256 + threadIdx.x;
    int pair = idx >> 10, off = idx & 1023;
    const float4* src = (const float4*)g_KVp + (size_t)pair * 8 * 1024 + off;
    float4 s = make_float4(0.f, 0.f, 0.f, 0.f);
#pragma unroll
    for (int k = 0; k < 8; k++) {
        float4 v = src[(size_t)k * 1024];
        s.x += v.x; s.y += v.y; s.z += v.z; s.w += v.w;
    }
    s.x *= SCALE; s.y *= SCALE; s.z *= SCALE; s.w *= SCALE;

    __half hi[4], lo[4];
    hi[0] = __float2half(s.x); lo[0] = __float2half(s.x - __half2float(hi[0]));
    hi[1] = __float2half(s.y); lo[1] = __float2half(s.y - __half2float(hi[1]));
    hi[2] = __float2half(s.z); lo[2] = __float2half(s.z - __half2float(hi[2]));
    hi[3] = __float2half(s.w); lo[3] = __float2half(s.w - __half2float(hi[3]));
    *(uint2*)(g_KVThi + 4 * (size_t)idx) = *(uint2*)hi;
    *(uint2*)(g_KVTlo + 4 * (size_t)idx) = *(uint2*)lo;
}

// ---------------------------------------------------------------------------
// Kernel C: out = q @ KV via HMMA, 128-row tiles (round-12 exact body)
// grid (64 pairs, 16 chunks of 128 rows), 256 threads
// ---------------------------------------------------------------------------
__global__ __launch_bounds__(256)
void out_gemm(float* __restrict__ out)
{
    cudaGridDependencySynchronize();          // wait: g_KVThi/lo (and g_Y16)

    extern __shared__ char smc[];
    const uint32_t sq  = smem_u32(smc);
    const uint32_t sbh = sq + 16384;
    const uint32_t sbl = sbh + 8192;

    const int pair = blockIdx.x;
    const int nc   = blockIdx.y;
    const int b = pair >> 4, h = pair & 15;
    const int tid = threadIdx.x;
    const int wid = tid >> 5, lid = tid & 31;

    const size_t rowBaseQ = (size_t)b * NSEQ + (size_t)nc * 128;
    const int qCol = h * HDIM;

#pragma unroll
    for (int i = 0; i < 4; i++) {
        int o = tid + i * 256;
        int r = o >> 3, ch = o & 7;
        uint32_t sw = r * 128 + ((ch ^ (r & 7)) << 4);
        cp16(sq + sw, g_Y16 + (rowBaseQ + r) * N_COLS + qCol + ch * 8);
    }
    const __half* kvh = g_KVThi + (size_t)pair * 4096;
    const __half* kvl = g_KVTlo + (size_t)pair * 4096;
#pragma unroll
    for (int i = 0; i < 2; i++) {
        int o = tid + i * 256;
        int r = o >> 3, ch = o & 7;
        uint32_t sw = r * 128 + ((ch ^ (r & 7)) << 4);
        cp16(sbh + sw, kvh + r * 64 + ch * 8);
        cp16(sbl + sw, kvl + r * 64 + ch * 8);
    }
    asm volatile("cp.async.commit_group;" ::: "memory");
    asm volatile("cp.async.wait_group 0;" ::: "memory");
    __syncthreads();

    float acc[8][4];
#pragma unroll
    for (int nt = 0; nt < 8; nt++)
#pragma unroll
        for (int j = 0; j < 4; j++) acc[nt][j] = 0.0f;

    const uint32_t aRowOff = (uint32_t)(wid * 16 + (lid & 15)) * 128;
    const uint32_t bRowOff = (uint32_t)((lid & 7) + ((lid >> 4) & 1) * 8) * 128;
    const int xorC   = lid & 7;
    const int chSelA = lid >> 4;
    const int chSelB = (lid >> 3) & 1;

#pragma unroll
    for (int ks = 0; ks < 4; ks++) {
        const uint32_t chA = (uint32_t)((ks * 2 + chSelA) ^ xorC) << 4;
        const uint32_t chB = (uint32_t)((ks * 2 + chSelB) ^ xorC) << 4;
        uint32_t a[4];
        ldsm4(a, sq + aRowOff + chA);
        uint32_t bh[4][4], bl[4][4];
#pragma unroll
        for (int p = 0; p < 4; p++) {
            ldsm4(bh[p], sbh + bRowOff + p * (16 * 128) + chB);
            ldsm4(bl[p], sbl + bRowOff + p * (16 * 128) + chB);
        }
#pragma unroll
        for (int p = 0; p < 4; p++) {
            hmma(acc[2 * p + 0], a, &bh[p][0]);
            hmma(acc[2 * p + 1], a, &bh[p][2]);
            hmma(acc[2 * p + 0], a, &bl[p][0]);
            hmma(acc[2 * p + 1], a, &bl[p][2]);
        }
    }

    float* obase = out + ((size_t)pair * NSEQ + (size_t)nc * 128) * HDIM;
    const int r0 = wid * 16 + (lid >> 2);
    const int ec = (lid & 3) * 2;
#pragma unroll
    for (int nt = 0; nt < 8; nt++) {
        *(float2*)&obase[(size_t)r0 * HDIM + ec + nt * 8] = *(float2*)&acc[nt][0];
        *(float2*)&obase[(size_t)(r0 + 8) * HDIM + ec + nt * 8] = *(float2*)&acc[nt][2];
    }
}

// ---------------------------------------------------------------------------
// Host launch: PDL-chained
// ---------------------------------------------------------------------------
static void launch_pdl(const void* fn, dim3 grid, dim3 block, size_t smem,
                       void** args)
{
    cudaLaunchConfig_t cfg = {};
    cfg.gridDim = grid;
    cfg.blockDim = block;
    cfg.dynamicSmemBytes = smem;
    cfg.stream = 0;
    cudaLaunchAttribute at[1];
    at[0].id = cudaLaunchAttributeProgrammaticStreamSerialization;
    at[0].val.programmaticStreamSerializationAllowed = 1;
    cfg.attrs = at;
    cfg.numAttrs = 1;
    cudaLaunchKernelExC(&cfg, fn, args);
}

extern "C" void kernel_launch(void* const* d_in, const int* in_sizes, int n_in,
                              void* d_out, int out_size)
{
    (void)in_sizes; (void)n_in; (void)out_size;
    const float* x    = (const float*)d_in[0];
    const float* W    = (const float*)d_in[1];
    const float* bias = (const float*)d_in[2];
    float* out = (float*)d_out;

    static int attr_set = 0;
    if (!attr_set) {
        cudaFuncSetAttribute(qkv_mma, cudaFuncAttributeMaxDynamicSharedMemorySize, SMEM_DYN);
        cudaFuncSetAttribute(kv_partial, cudaFuncAttributeMaxDynamicSharedMemorySize, KVP_SMEM);
        cudaFuncSetAttribute(out_gemm, cudaFuncAttributeMaxDynamicSharedMemorySize, OUT_SMEM);
        attr_set = 1;
    }

    // conv_x: normal launch (head of chain)
    conv_x<<<(M_ROWS * K_DIM / 4) / 256, 256>>>((const float4*)x);

    // conv_w: PDL, no device-side sync -> overlaps conv_x fully
    {
        const float* a0 = W; const float* a1 = bias;
        void* args[] = { (void*)&a0, (void*)&a1 };
        launch_pdl((const void*)conv_w, dim3(16, 32), dim3(256), 0, args);
    }
    // qkv: PDL + sync (pre-launch overlaps conv tail)
    launch_pdl((const void*)qkv_mma, dim3(N_COLS / QBN, M_ROWS / QBM), dim3(256),
               SMEM_DYN, nullptr);
    // kv_partial: PDL + sync
    launch_pdl((const void*)kv_partial, dim3(64, 8), dim3(128), KVP_SMEM, nullptr);
    // kv_reduce: PDL + sync
    launch_pdl((const void*)kv_reduce, dim3(256), dim3(256), 0, nullptr);
    // out_gemm: PDL + sync
    {
        float* a0 = out;
        void* args[] = { (void*)&a0 };
        launch_pdl((const void*)out_gemm, dim3(64, 16), dim3(256), OUT_SMEM, args);
    }
}

// round 15
// speedup vs baseline: 1.4782x; 1.4782x over previous
#include <cuda_runtime.h>
#include <cuda_fp16.h>
#include <cstdint>

// ---------------------------------------------------------------------------
// Problem constants
// ---------------------------------------------------------------------------
#define BATCH   4
#define NSEQ    2048
#define DIM     1024
#define HEADS   16
#define HDIM    64
#define M_ROWS  8192
#define N_COLS  3072
#define K_DIM   1024
#define SCALE   32.0f

// qkv GEMM tiling (round-6 proven: CTA 128x128, 8 warps 4x2, 3 stages, 2 CTAs/SM)
#define QBM 128
#define QBN 128
#define KCH 64
#define NCHUNK (K_DIM / KCH)
#define STAGE_BYTES 32768
#define NSTAGE 3
#define SMEM_DYN (NSTAGE * STAGE_BYTES)

// kv_partial pipeline (round-12): 8 splits x 256 rows; 8 subtiles, 3 stages
#define KVP_STAGE 8192
#define KVP_SMEM (3 * KVP_STAGE)     // 24576

#define OUT_SMEM 32768               // q 16KB + KVT hi 8KB + KVT lo 8KB

// ---------------------------------------------------------------------------
// Scratch (device globals — allocation-free per harness rules)
// ---------------------------------------------------------------------------
__device__ __align__(16) __half g_Ah[(size_t)M_ROWS * K_DIM];      // fp16(x)
__device__ __align__(16) __half g_Bh[(size_t)N_COLS * K_DIM];      // W^T permuted fp16
__device__ float g_biasP[N_COLS];
// Y fp16, permuted: [row][t*1024 + h*64 + d]
__device__ __align__(16) __half g_Y16[(size_t)M_ROWS * N_COLS];
__device__ float g_KVp[64 * 8 * HDIM * HDIM];                      // KV^T partials [d2][d1]
__device__ __align__(16) __half g_KVThi[64 * HDIM * HDIM];
__device__ __align__(16) __half g_KVTlo[64 * HDIM * HDIM];

// ---------------------------------------------------------------------------
// Inline PTX (valid on base sm_103 target)
// ---------------------------------------------------------------------------
__device__ __forceinline__ uint32_t smem_u32(const void* p) {
    uint32_t a;
    asm("{ .reg .u64 t; cvta.to.shared.u64 t, %1; cvt.u32.u64 %0, t; }" : "=r"(a) : "l"(p));
    return a;
}
__device__ __forceinline__ void cp16(uint32_t dst, const void* src) {
    asm volatile("cp.async.cg.shared.global [%0], [%1], 16;" :: "r"(dst), "l"(src));
}
__device__ __forceinline__ void ldsm4(uint32_t* r, uint32_t addr) {
    asm volatile("ldmatrix.sync.aligned.m8n8.x4.shared.b16 {%0,%1,%2,%3}, [%4];"
        : "=r"(r[0]), "=r"(r[1]), "=r"(r[2]), "=r"(r[3]) : "r"(addr));
}
__device__ __forceinline__ void ldsm4t(uint32_t* r, uint32_t addr) {
    asm volatile("ldmatrix.sync.aligned.m8n8.x4.trans.shared.b16 {%0,%1,%2,%3}, [%4];"
        : "=r"(r[0]), "=r"(r[1]), "=r"(r[2]), "=r"(r[3]) : "r"(addr));
}
__device__ __forceinline__ void hmma(float* d, const uint32_t* a, const uint32_t* b) {
    asm volatile("mma.sync.aligned.m16n8k16.row.col.f32.f16.f16.f32 "
        "{%0,%1,%2,%3}, {%4,%5,%6,%7}, {%8,%9}, {%0,%1,%2,%3};"
        : "+f"(d[0]), "+f"(d[1]), "+f"(d[2]), "+f"(d[3])
        : "r"(a[0]), "r"(a[1]), "r"(a[2]), "r"(a[3]), "r"(b[0]), "r"(b[1]));
}

// ---------------------------------------------------------------------------
// conv_x: fp32 x -> fp16 (no smem -> full occupancy)
// ---------------------------------------------------------------------------
__global__ __launch_bounds__(256)
void conv_x(const float4* __restrict__ x)
{
    size_t i = (size_t)blockIdx.x * 256 + threadIdx.x;
    float4 v = x[i];
    __half h[4];
    h[0] = __float2half(v.x); h[1] = __float2half(v.y);
    h[2] = __float2half(v.z); h[3] = __float2half(v.w);
    *(uint2*)(g_Ah + 4 * i) = *(uint2*)h;
}

// ---------------------------------------------------------------------------
// conv_w: W [k][c] -> permuted transposed fp16 g_Bh[c'][k]; folds bias permute
// c = h*192 + d*3 + t  ->  c' = t*1024 + h*64 + d
// ---------------------------------------------------------------------------
__global__ __launch_bounds__(256)
void conv_w(const float* __restrict__ W, const float* __restrict__ bias)
{
    __shared__ float tile[32][193];
    const int h  = blockIdx.x;
    const int k0 = blockIdx.y * 32;
    const int tid = threadIdx.x;

    if (blockIdx.y == 0 && tid < 192) {
        int d = tid & 63, t = tid >> 6;
        g_biasP[t * 1024 + h * 64 + d] = bias[h * 192 + d * 3 + t];
    }

    for (int e = tid; e < 32 * 192; e += 256) {
        int r = e / 192, cc = e % 192;
        tile[r][cc] = W[(size_t)(k0 + r) * N_COLS + h * 192 + cc];
    }
    __syncthreads();

    for (int e = tid; e < 3 * 64 * 32; e += 256) {
        int t = e >> 11;
        int rem = e & 2047;
        int d = rem >> 5, kk = rem & 31;
        float v = tile[kk][d * 3 + t];
        g_Bh[(size_t)(t * 1024 + h * 64 + d) * K_DIM + k0 + kk] = __float2half(v);
    }
}

// ---------------------------------------------------------------------------
// Kernel A: Y16 = fp16(X @ W' + bias') via mma.sync fp16 (round-6 exact)
// grid (24, 64), 256 threads (8 warps, 4x2), 2 CTAs/SM
// ---------------------------------------------------------------------------
__device__ __forceinline__ void load_chunk(uint32_t stage_sb, int rowBase, int colBase,
                                           int k0, int tid)
{
#pragma unroll
    for (int i = 0; i < 4; i++) {
        int o = tid + i * 256;
        int r = o >> 3, ch = o & 7;
        cp16(stage_sb + r * 128 + ((ch ^ (r & 7)) << 4),
             g_Ah + (size_t)(rowBase + r) * K_DIM + k0 + ch * 8);
    }
#pragma unroll
    for (int i = 0; i < 4; i++) {
        int o = tid + i * 256;
        int r = o >> 3, ch = o & 7;
        cp16(stage_sb + 16384 + r * 128 + ((ch ^ (r & 7)) << 4),
             g_Bh + (size_t)(colBase + r) * K_DIM + k0 + ch * 8);
    }
}

__global__ __launch_bounds__(256, 2)
void qkv_mma()
{
    extern __shared__ char smem[];
    const uint32_t sb = smem_u32(smem);
    const int tid = threadIdx.x;
    const int wid = tid >> 5, lid = tid & 31;
    const int warp_m = wid >> 1, warp_n = wid & 1;
    const int rowBase = blockIdx.y * QBM;
    const int colBase = blockIdx.x * QBN;

    float acc[2][8][4];
#pragma unroll
    for (int mt = 0; mt < 2; mt++)
#pragma unroll
        for (int nt = 0; nt < 8; nt++)
#pragma unroll
            for (int j = 0; j < 4; j++) acc[mt][nt][j] = 0.0f;

#pragma unroll
    for (int c = 0; c < NSTAGE; c++) {
        load_chunk(sb + c * STAGE_BYTES, rowBase, colBase, c * KCH, tid);
        asm volatile("cp.async.commit_group;" ::: "memory");
    }

    const uint32_t aRowOff = (uint32_t)(warp_m * 32 + (lid & 15)) * 128;
    const uint32_t bRowOff = (uint32_t)(warp_n * 64 + (lid & 7) + ((lid >> 4) & 1) * 8) * 128;
    const int xorC   = lid & 7;
    const int chSelA = lid >> 4;
    const int chSelB = (lid >> 3) & 1;

    for (int c = 0; c < NCHUNK; c++) {
        asm volatile("cp.async.wait_group 2;" ::: "memory");
        __syncthreads();
        const uint32_t st = sb + (uint32_t)(c % NSTAGE) * STAGE_BYTES;

#pragma unroll
        for (int ks = 0; ks < 4; ks++) {
            const uint32_t chA = (uint32_t)((ks * 2 + chSelA) ^ xorC) << 4;
            const uint32_t chB = (uint32_t)((ks * 2 + chSelB) ^ xorC) << 4;
            uint32_t ah[2][4];
#pragma unroll
            for (int mt = 0; mt < 2; mt++)
                ldsm4(ah[mt], st + aRowOff + mt * (16 * 128) + chA);
            uint32_t bh[4][4];
#pragma unroll
            for (int p = 0; p < 4; p++)
                ldsm4(bh[p], st + 16384 + bRowOff + p * (16 * 128) + chB);
#pragma unroll
            for (int mt = 0; mt < 2; mt++)
#pragma unroll
                for (int p = 0; p < 4; p++) {
                    hmma(acc[mt][2 * p + 0], ah[mt], &bh[p][0]);
                    hmma(acc[mt][2 * p + 1], ah[mt], &bh[p][2]);
                }
        }
        __syncthreads();
        if (c + NSTAGE < NCHUNK)
            load_chunk(st, rowBase, colBase, (c + NSTAGE) * KCH, tid);
        asm volatile("cp.async.commit_group;" ::: "memory");
    }

    // Epilogue: + bias -> fp16 Y
    const int er = rowBase + warp_m * 32 + (lid >> 2);
    const int ec = colBase + warp_n * 64 + (lid & 3) * 2;
    float2 bb[8];
#pragma unroll
    for (int nt = 0; nt < 8; nt++) bb[nt] = *(const float2*)&g_biasP[ec + nt * 8];
#pragma unroll
    for (int mt = 0; mt < 2; mt++) {
        const int r0 = er + mt * 16;
#pragma unroll
        for (int nt = 0; nt < 8; nt++) {
            __half2 v0 = __floats2half2_rn(acc[mt][nt][0] + bb[nt].x,
                                           acc[mt][nt][1] + bb[nt].y);
            __half2 v1 = __floats2half2_rn(acc[mt][nt][2] + bb[nt].x,
                                           acc[mt][nt][3] + bb[nt].y);
            *(__half2*)&g_Y16[(size_t)r0 * N_COLS + ec + nt * 8] = v0;
            *(__half2*)&g_Y16[(size_t)(r0 + 8) * N_COLS + ec + nt * 8] = v1;
        }
    }
}

// ---------------------------------------------------------------------------
// Kernel B: KV^T partials via HMMA, 3-stage pipelined 32-row subtiles
// grid (64, 8), 128 threads, 24KB smem (round-12 exact)
// ---------------------------------------------------------------------------
__device__ __forceinline__ void kvp_load_sub(uint32_t stg, size_t rowBase, int s,
                                             int vCol, int kCol, int tid)
{
#pragma unroll
    for (int i = 0; i < 4; i++) {
        int o = tid + i * 128;
        int t = o >> 8;
        int r = (o >> 3) & 31;
        int ch = o & 7;
        uint32_t sw = stg + t * 4096 + r * 128 + ((ch ^ (r & 7)) << 4);
        cp16(sw, g_Y16 + (rowBase + s * 32 + r) * N_COLS
                  + (t ? kCol : vCol) + ch * 8);
    }
}

__global__ __launch_bounds__(128)
void kv_partial()
{
    extern __shared__ char smc[];
    const uint32_t sbase = smem_u32(smc);
    const int pair  = blockIdx.x;
    const int split = blockIdx.y;
    const int b = pair >> 4, h = pair & 15;
    const int tid = threadIdx.x;
    const int wid = tid >> 5, lid = tid & 31;

    const size_t rowBase = (size_t)b * NSEQ + (size_t)split * 256;
    const int kCol = 1024 + h * HDIM;
    const int vCol = 2048 + h * HDIM;

    kvp_load_sub(sbase,             rowBase, 0, vCol, kCol, tid);
    asm volatile("cp.async.commit_group;" ::: "memory");
    kvp_load_sub(sbase + KVP_STAGE, rowBase, 1, vCol, kCol, tid);
    asm volatile("cp.async.commit_group;" ::: "memory");

    float acc[4][2][4];
#pragma unroll
    for (int mt = 0; mt < 4; mt++)
#pragma unroll
        for (int bn = 0; bn < 2; bn++)
#pragma unroll
            for (int j = 0; j < 4; j++) acc[mt][bn][j] = 0.0f;

    const int krA = (lid & 7) | ((lid & 16) >> 1);
    const int mSel = (lid >> 3) & 1;
    const int krB = lid & 15;
    const int nSel = lid >> 4;
    const int xA = krA & 7;
    const int xB = krB & 7;

    for (int s = 0; s < 8; s++) {
        if (s < 7) { asm volatile("cp.async.wait_group 1;" ::: "memory"); }
        else       { asm volatile("cp.async.wait_group 0;" ::: "memory"); }
        __syncthreads();

        if (s + 2 < 8) {
            kvp_load_sub(sbase + (uint32_t)((s + 2) % 3) * KVP_STAGE,
                         rowBase, s + 2, vCol, kCol, tid);
            asm volatile("cp.async.commit_group;" ::: "memory");
        }

        const uint32_t stV = sbase + (uint32_t)(s % 3) * KVP_STAGE;
        const uint32_t stK = stV + 4096;
#pragma unroll
        for (int kl = 0; kl < 2; kl++) {
            const int rowA = kl * 16 + krA;
            const int rowB = kl * 16 + krB;
            uint32_t a[4][4];
#pragma unroll
            for (int mt = 0; mt < 4; mt++) {
                uint32_t ch = (uint32_t)((mt * 2 + mSel) ^ xA) << 4;
                ldsm4t(a[mt], stV + rowA * 128 + ch);
            }
            uint32_t bf[4];
            {
                uint32_t ch = (uint32_t)((wid * 2 + nSel) ^ xB) << 4;
                ldsm4t(bf, stK + rowB * 128 + ch);
            }
#pragma unroll
            for (int mt = 0; mt < 4; mt++) {
                hmma(acc[mt][0], a[mt], &bf[0]);
                hmma(acc[mt][1], a[mt], &bf[2]);
            }
        }
    }

    float* dst = g_KVp + ((size_t)pair * 8 + split) * (HDIM * HDIM);
    const int d1c = wid * 16 + (lid & 3) * 2;
#pragma unroll
    for (int mt = 0; mt < 4; mt++) {
        const int d2r = mt * 16 + (lid >> 2);
#pragma unroll
        for (int bn = 0; bn < 2; bn++) {
            *(float2*)&dst[(size_t)d2r * HDIM + d1c + bn * 8] =
                *(float2*)&acc[mt][bn][0];
            *(float2*)&dst[(size_t)(d2r + 8) * HDIM + d1c + bn * 8] =
                *(float2*)&acc[mt][bn][2];
        }
    }
}

// ---------------------------------------------------------------------------
// kv_reduce: float4-vectorized; sum 8 splits, scale, emit fp16 hi+lo
// ---------------------------------------------------------------------------
__global__ __launch_bounds__(256)
void kv_reduce()
{
    int idx = blockIdx.x * 256 + threadIdx.x;
    int pair = idx >> 10, off = idx & 1023;
    const float4* src = (const float4*)g_KVp + (size_t)pair * 8 * 1024 + off;
    float4 s = make_float4(0.f, 0.f, 0.f, 0.f);
#pragma unroll
    for (int k = 0; k < 8; k++) {
        float4 v = src[(size_t)k * 1024];
        s.x += v.x; s.y += v.y; s.z += v.z; s.w += v.w;
    }
    s.x *= SCALE; s.y *= SCALE; s.z *= SCALE; s.w *= SCALE;

    __half hi[4], lo[4];
    hi[0] = __float2half(s.x); lo[0] = __float2half(s.x - __half2float(hi[0]));
    hi[1] = __float2half(s.y); lo[1] = __float2half(s.y - __half2float(hi[1]));
    hi[2] = __float2half(s.z); lo[2] = __float2half(s.z - __half2float(hi[2]));
    hi[3] = __float2half(s.w); lo[3] = __float2half(s.w - __half2float(hi[3]));
    *(uint2*)(g_KVThi + 4 * (size_t)idx) = *(uint2*)hi;
    *(uint2*)(g_KVTlo + 4 * (size_t)idx) = *(uint2*)lo;
}

// ---------------------------------------------------------------------------
// Kernel C: out = q @ KV via HMMA, 128-row tiles (round-12 exact)
// grid (64 pairs, 16 chunks of 128 rows), 256 threads
// ---------------------------------------------------------------------------
__global__ __launch_bounds__(256)
void out_gemm(float* __restrict__ out)
{
    extern __shared__ char smc[];
    const uint32_t sq  = smem_u32(smc);
    const uint32_t sbh = sq + 16384;
    const uint32_t sbl = sbh + 8192;

    const int pair = blockIdx.x;
    const int nc   = blockIdx.y;
    const int b = pair >> 4, h = pair & 15;
    const int tid = threadIdx.x;
    const int wid = tid >> 5, lid = tid & 31;

    const size_t rowBaseQ = (size_t)b * NSEQ + (size_t)nc * 128;
    const int qCol = h * HDIM;

#pragma unroll
    for (int i = 0; i < 4; i++) {
        int o = tid + i * 256;
        int r = o >> 3, ch = o & 7;
        uint32_t sw = r * 128 + ((ch ^ (r & 7)) << 4);
        cp16(sq + sw, g_Y16 + (rowBaseQ + r) * N_COLS + qCol + ch * 8);
    }
    const __half* kvh = g_KVThi + (size_t)pair * 4096;
    const __half* kvl = g_KVTlo + (size_t)pair * 4096;
#pragma unroll
    for (int i = 0; i < 2; i++) {
        int o = tid + i * 256;
        int r = o >> 3, ch = o & 7;
        uint32_t sw = r * 128 + ((ch ^ (r & 7)) << 4);
        cp16(sbh + sw, kvh + r * 64 + ch * 8);
        cp16(sbl + sw, kvl + r * 64 + ch * 8);
    }
    asm volatile("cp.async.commit_group;" ::: "memory");
    asm volatile("cp.async.wait_group 0;" ::: "memory");
    __syncthreads();

    float acc[8][4];
#pragma unroll
    for (int nt = 0; nt < 8; nt++)
#pragma unroll
        for (int j = 0; j < 4; j++) acc[nt][j] = 0.0f;

    const uint32_t aRowOff = (uint32_t)(wid * 16 + (lid & 15)) * 128;
    const uint32_t bRowOff = (uint32_t)((lid & 7) + ((lid >> 4) & 1) * 8) * 128;
    const int xorC   = lid & 7;
    const int chSelA = lid >> 4;
    const int chSelB = (lid >> 3) & 1;

#pragma unroll
    for (int ks = 0; ks < 4; ks++) {
        const uint32_t chA = (uint32_t)((ks * 2 + chSelA) ^ xorC) << 4;
        const uint32_t chB = (uint32_t)((ks * 2 + chSelB) ^ xorC) << 4;
        uint32_t a[4];
        ldsm4(a, sq + aRowOff + chA);
        uint32_t bh[4][4], bl[4][4];
#pragma unroll
        for (int p = 0; p < 4; p++) {
            ldsm4(bh[p], sbh + bRowOff + p * (16 * 128) + chB);
            ldsm4(bl[p], sbl + bRowOff + p * (16 * 128) + chB);
        }
#pragma unroll
        for (int p = 0; p < 4; p++) {
            hmma(acc[2 * p + 0], a, &bh[p][0]);
            hmma(acc[2 * p + 1], a, &bh[p][2]);
            hmma(acc[2 * p + 0], a, &bl[p][0]);
            hmma(acc[2 * p + 1], a, &bl[p][2]);
        }
    }

    float* obase = out + ((size_t)pair * NSEQ + (size_t)nc * 128) * HDIM;
    const int r0 = wid * 16 + (lid >> 2);
    const int ec = (lid & 3) * 2;
#pragma unroll
    for (int nt = 0; nt < 8; nt++) {
        *(float2*)&obase[(size_t)r0 * HDIM + ec + nt * 8] = *(float2*)&acc[nt][0];
        *(float2*)&obase[(size_t)(r0 + 8) * HDIM + ec + nt * 8] = *(float2*)&acc[nt][2];
    }
}

// ---------------------------------------------------------------------------
// Host launch: round-12 schedule + conv_x/conv_w fork-join on a side stream
// ---------------------------------------------------------------------------
extern "C" void kernel_launch(void* const* d_in, const int* in_sizes, int n_in,
                              void* d_out, int out_size)
{
    (void)in_sizes; (void)n_in; (void)out_size;
    const float* x    = (const float*)d_in[0];
    const float* W    = (const float*)d_in[1];
    const float* bias = (const float*)d_in[2];
    float* out = (float*)d_out;

    static int attr_set = 0;
    static cudaStream_t s1 = 0;
    static cudaEvent_t evFork = 0, evJoin = 0;
    static int fork_ok = 0;
    if (!attr_set) {
        cudaFuncSetAttribute(qkv_mma, cudaFuncAttributeMaxDynamicSharedMemorySize, SMEM_DYN);
        cudaFuncSetAttribute(kv_partial, cudaFuncAttributeMaxDynamicSharedMemorySize, KVP_SMEM);
        cudaFuncSetAttribute(out_gemm, cudaFuncAttributeMaxDynamicSharedMemorySize, OUT_SMEM);
        if (cudaStreamCreateWithFlags(&s1, cudaStreamNonBlocking) == cudaSuccess &&
            cudaEventCreateWithFlags(&evFork, cudaEventDisableTiming) == cudaSuccess &&
            cudaEventCreateWithFlags(&evJoin, cudaEventDisableTiming) == cudaSuccess)
            fork_ok = 1;
        attr_set = 1;
    }

    if (fork_ok) {
        // Fork: conv_w runs on side stream concurrently with conv_x
        cudaEventRecord(evFork, 0);
        cudaStreamWaitEvent(s1, evFork, 0);
        conv_w<<<dim3(16, 32), 256, 0, s1>>>(W, bias);
        cudaEventRecord(evJoin, s1);
        conv_x<<<(M_ROWS * K_DIM / 4) / 256, 256>>>((const float4*)x);
        cudaStreamWaitEvent(0, evJoin, 0);
    } else {
        conv_x<<<(M_ROWS * K_DIM / 4) / 256, 256>>>((const float4*)x);
        conv_w<<<dim3(16, 32), 256>>>(W, bias);
    }

    qkv_mma<<<dim3(N_COLS / QBN, M_ROWS / QBM), 256, SMEM_DYN>>>();

    kv_partial<<<dim3(64, 8), 128, KVP_SMEM>>>();
    kv_reduce<<<256, 256>>>();
    out_gemm<<<dim3(64, 16), 256, OUT_SMEM>>>(out);
}

// round 16
// speedup vs baseline: 1.5879x; 1.0742x over previous
#include <cuda_runtime.h>
#include <cuda_fp16.h>
#include <cstdint>

// ---------------------------------------------------------------------------
// Problem constants
// ---------------------------------------------------------------------------
#define BATCH   4
#define NSEQ    2048
#define DIM     1024
#define HEADS   16
#define HDIM    64
#define M_ROWS  8192
#define N_COLS  3072
#define K_DIM   1024
#define SCALE   32.0f

// qkv GEMM tiling (round-6 proven: CTA 128x128, 8 warps 4x2, 3 stages, 2 CTAs/SM)
#define QBM 128
#define QBN 128
#define KCH 64
#define NCHUNK (K_DIM / KCH)
#define STAGE_BYTES 32768
#define NSTAGE 3
#define SMEM_DYN (NSTAGE * STAGE_BYTES)

// kv_partial pipeline (round-12): 8 splits x 256 rows; 8 subtiles, 3 stages
#define KVP_STAGE 8192
#define KVP_SMEM (3 * KVP_STAGE)     // 24576

#define OUT_SMEM 32768               // q 16KB + KVT hi 8KB + KVT lo 8KB

// ---------------------------------------------------------------------------
// Scratch (device globals — allocation-free per harness rules)
// ---------------------------------------------------------------------------
__device__ __align__(16) __half g_Ah[(size_t)M_ROWS * K_DIM];      // fp16(x)
__device__ __align__(16) __half g_Bh[(size_t)N_COLS * K_DIM];      // W^T permuted fp16
__device__ float g_biasP[N_COLS];
// Y packed by (plane, pair): index ((t*64 + b*16 + h) * 2048 + n) * 64 + d
//   t: 0=q, 1=k, 2=v ;  pair = b*16+h ;  each (t,pair) block = 256KB contiguous
__device__ __align__(16) __half g_Ypack[(size_t)3 * 64 * NSEQ * HDIM];
__device__ float g_KVp[64 * 8 * HDIM * HDIM];                      // KV^T partials [d2][d1]
__device__ __align__(16) __half g_KVThi[64 * HDIM * HDIM];
__device__ __align__(16) __half g_KVTlo[64 * HDIM * HDIM];

// ---------------------------------------------------------------------------
// Inline PTX (valid on base sm_103 target)
// ---------------------------------------------------------------------------
__device__ __forceinline__ uint32_t smem_u32(const void* p) {
    uint32_t a;
    asm("{ .reg .u64 t; cvta.to.shared.u64 t, %1; cvt.u32.u64 %0, t; }" : "=r"(a) : "l"(p));
    return a;
}
__device__ __forceinline__ void cp16(uint32_t dst, const void* src) {
    asm volatile("cp.async.cg.shared.global [%0], [%1], 16;" :: "r"(dst), "l"(src));
}
__device__ __forceinline__ void ldsm4(uint32_t* r, uint32_t addr) {
    asm volatile("ldmatrix.sync.aligned.m8n8.x4.shared.b16 {%0,%1,%2,%3}, [%4];"
        : "=r"(r[0]), "=r"(r[1]), "=r"(r[2]), "=r"(r[3]) : "r"(addr));
}
__device__ __forceinline__ void ldsm4t(uint32_t* r, uint32_t addr) {
    asm volatile("ldmatrix.sync.aligned.m8n8.x4.trans.shared.b16 {%0,%1,%2,%3}, [%4];"
        : "=r"(r[0]), "=r"(r[1]), "=r"(r[2]), "=r"(r[3]) : "r"(addr));
}
__device__ __forceinline__ void hmma(float* d, const uint32_t* a, const uint32_t* b) {
    asm volatile("mma.sync.aligned.m16n8k16.row.col.f32.f16.f16.f32 "
        "{%0,%1,%2,%3}, {%4,%5,%6,%7}, {%8,%9}, {%0,%1,%2,%3};"
        : "+f"(d[0]), "+f"(d[1]), "+f"(d[2]), "+f"(d[3])
        : "r"(a[0]), "r"(a[1]), "r"(a[2]), "r"(a[3]), "r"(b[0]), "r"(b[1]));
}

// ---------------------------------------------------------------------------
// conv_x: fp32 x -> fp16 (no smem -> full occupancy)
// ---------------------------------------------------------------------------
__global__ __launch_bounds__(256)
void conv_x(const float4* __restrict__ x)
{
    size_t i = (size_t)blockIdx.x * 256 + threadIdx.x;
    float4 v = x[i];
    __half h[4];
    h[0] = __float2half(v.x); h[1] = __float2half(v.y);
    h[2] = __float2half(v.z); h[3] = __float2half(v.w);
    *(uint2*)(g_Ah + 4 * i) = *(uint2*)h;
}

// ---------------------------------------------------------------------------
// conv_w: W [k][c] -> permuted transposed fp16 g_Bh[c'][k]; folds bias permute
// c = h*192 + d*3 + t  ->  c' = t*1024 + h*64 + d
// ---------------------------------------------------------------------------
__global__ __launch_bounds__(256)
void conv_w(const float* __restrict__ W, const float* __restrict__ bias)
{
    __shared__ float tile[32][193];
    const int h  = blockIdx.x;
    const int k0 = blockIdx.y * 32;
    const int tid = threadIdx.x;

    if (blockIdx.y == 0 && tid < 192) {
        int d = tid & 63, t = tid >> 6;
        g_biasP[t * 1024 + h * 64 + d] = bias[h * 192 + d * 3 + t];
    }

    for (int e = tid; e < 32 * 192; e += 256) {
        int r = e / 192, cc = e % 192;
        tile[r][cc] = W[(size_t)(k0 + r) * N_COLS + h * 192 + cc];
    }
    __syncthreads();

    for (int e = tid; e < 3 * 64 * 32; e += 256) {
        int t = e >> 11;
        int rem = e & 2047;
        int d = rem >> 5, kk = rem & 31;
        float v = tile[kk][d * 3 + t];
        g_Bh[(size_t)(t * 1024 + h * 64 + d) * K_DIM + k0 + kk] = __float2half(v);
    }
}

// ---------------------------------------------------------------------------
// Kernel A: qkv projection via mma.sync fp16; epilogue stores PACKED layout
// grid (24, 64), 256 threads (8 warps, 4x2), 2 CTAs/SM
// ---------------------------------------------------------------------------
__device__ __forceinline__ void load_chunk(uint32_t stage_sb, int rowBase, int colBase,
                                           int k0, int tid)
{
#pragma unroll
    for (int i = 0; i < 4; i++) {
        int o = tid + i * 256;
        int r = o >> 3, ch = o & 7;
        cp16(stage_sb + r * 128 + ((ch ^ (r & 7)) << 4),
             g_Ah + (size_t)(rowBase + r) * K_DIM + k0 + ch * 8);
    }
#pragma unroll
    for (int i = 0; i < 4; i++) {
        int o = tid + i * 256;
        int r = o >> 3, ch = o & 7;
        cp16(stage_sb + 16384 + r * 128 + ((ch ^ (r & 7)) << 4),
             g_Bh + (size_t)(colBase + r) * K_DIM + k0 + ch * 8);
    }
}

__global__ __launch_bounds__(256, 2)
void qkv_mma()
{
    extern __shared__ char smem[];
    const uint32_t sb = smem_u32(smem);
    const int tid = threadIdx.x;
    const int wid = tid >> 5, lid = tid & 31;
    const int warp_m = wid >> 1, warp_n = wid & 1;
    const int rowBase = blockIdx.y * QBM;
    const int colBase = blockIdx.x * QBN;

    float acc[2][8][4];
#pragma unroll
    for (int mt = 0; mt < 2; mt++)
#pragma unroll
        for (int nt = 0; nt < 8; nt++)
#pragma unroll
            for (int j = 0; j < 4; j++) acc[mt][nt][j] = 0.0f;

#pragma unroll
    for (int c = 0; c < NSTAGE; c++) {
        load_chunk(sb + c * STAGE_BYTES, rowBase, colBase, c * KCH, tid);
        asm volatile("cp.async.commit_group;" ::: "memory");
    }

    const uint32_t aRowOff = (uint32_t)(warp_m * 32 + (lid & 15)) * 128;
    const uint32_t bRowOff = (uint32_t)(warp_n * 64 + (lid & 7) + ((lid >> 4) & 1) * 8) * 128;
    const int xorC   = lid & 7;
    const int chSelA = lid >> 4;
    const int chSelB = (lid >> 3) & 1;

    for (int c = 0; c < NCHUNK; c++) {
        asm volatile("cp.async.wait_group 2;" ::: "memory");
        __syncthreads();
        const uint32_t st = sb + (uint32_t)(c % NSTAGE) * STAGE_BYTES;

#pragma unroll
        for (int ks = 0; ks < 4; ks++) {
            const uint32_t chA = (uint32_t)((ks * 2 + chSelA) ^ xorC) << 4;
            const uint32_t chB = (uint32_t)((ks * 2 + chSelB) ^ xorC) << 4;
            uint32_t ah[2][4];
#pragma unroll
            for (int mt = 0; mt < 2; mt++)
                ldsm4(ah[mt], st + aRowOff + mt * (16 * 128) + chA);
            uint32_t bh[4][4];
#pragma unroll
            for (int p = 0; p < 4; p++)
                ldsm4(bh[p], st + 16384 + bRowOff + p * (16 * 128) + chB);
#pragma unroll
            for (int mt = 0; mt < 2; mt++)
#pragma unroll
                for (int p = 0; p < 4; p++) {
                    hmma(acc[mt][2 * p + 0], ah[mt], &bh[p][0]);
                    hmma(acc[mt][2 * p + 1], ah[mt], &bh[p][2]);
                }
        }
        __syncthreads();
        if (c + NSTAGE < NCHUNK)
            load_chunk(st, rowBase, colBase, (c + NSTAGE) * KCH, tid);
        asm volatile("cp.async.commit_group;" ::: "memory");
    }

    // Epilogue: + bias -> PACKED fp16 Y
    // This warp's 64-col sub-tile lies in exactly one (t, h) plane:
    const int ec0 = colBase + warp_n * 64;            // permuted col base
    const int t_  = ec0 >> 10;                        // 0=q,1=k,2=v
    const int h_  = (ec0 & 1023) >> 6;                // head
    const int b_  = rowBase >> 11;                    // batch (tile never straddles)
    const int nBase = (rowBase & 2047) + warp_m * 32 + (lid >> 2);
    const int dBase = (lid & 3) * 2;
    __half* ybase = g_Ypack + ((size_t)(t_ * 64 + b_ * 16 + h_) * NSEQ) * HDIM;

    float2 bb[8];
#pragma unroll
    for (int nt = 0; nt < 8; nt++) bb[nt] = *(const float2*)&g_biasP[ec0 + dBase + nt * 8];
#pragma unroll
    for (int mt = 0; mt < 2; mt++) {
        const int n0 = nBase + mt * 16;
#pragma unroll
        for (int nt = 0; nt < 8; nt++) {
            __half2 v0 = __floats2half2_rn(acc[mt][nt][0] + bb[nt].x,
                                           acc[mt][nt][1] + bb[nt].y);
            __half2 v1 = __floats2half2_rn(acc[mt][nt][2] + bb[nt].x,
                                           acc[mt][nt][3] + bb[nt].y);
            *(__half2*)&ybase[(size_t)n0 * HDIM + dBase + nt * 8] = v0;
            *(__half2*)&ybase[(size_t)(n0 + 8) * HDIM + dBase + nt * 8] = v1;
        }
    }
}

// ---------------------------------------------------------------------------
// Kernel B: KV^T partials via HMMA; contiguous packed reads
// grid (64, 8), 128 threads, 24KB smem
// ---------------------------------------------------------------------------
__device__ __forceinline__ void kvp_load_sub(uint32_t stg, const __half* kbase,
                                             const __half* vbase, int n0, int s, int tid)
{
    // 32 rows x 8 ch x {v,k} = 512 cp16, 4 per thread; v at +0, k at +4096
#pragma unroll
    for (int i = 0; i < 4; i++) {
        int o = tid + i * 128;
        int t = o >> 8;                     // 0 = v, 1 = k
        int r = (o >> 3) & 31;
        int ch = o & 7;
        uint32_t sw = stg + t * 4096 + r * 128 + ((ch ^ (r & 7)) << 4);
        const __half* src = (t ? kbase : vbase) + (size_t)(n0 + s * 32 + r) * HDIM + ch * 8;
        cp16(sw, src);
    }
}

__global__ __launch_bounds__(128)
void kv_partial()
{
    extern __shared__ char smc[];
    const uint32_t sbase = smem_u32(smc);
    const int pair  = blockIdx.x;
    const int split = blockIdx.y;
    const int tid = threadIdx.x;
    const int wid = tid >> 5, lid = tid & 31;

    const int n0 = split * 256;
    const __half* kbase = g_Ypack + ((size_t)(64 + pair) * NSEQ) * HDIM;   // t=1 plane
    const __half* vbase = g_Ypack + ((size_t)(128 + pair) * NSEQ) * HDIM;  // t=2 plane

    kvp_load_sub(sbase,             kbase, vbase, n0, 0, tid);
    asm volatile("cp.async.commit_group;" ::: "memory");
    kvp_load_sub(sbase + KVP_STAGE, kbase, vbase, n0, 1, tid);
    asm volatile("cp.async.commit_group;" ::: "memory");

    float acc[4][2][4];
#pragma unroll
    for (int mt = 0; mt < 4; mt++)
#pragma unroll
        for (int bn = 0; bn < 2; bn++)
#pragma unroll
            for (int j = 0; j < 4; j++) acc[mt][bn][j] = 0.0f;

    const int krA = (lid & 7) | ((lid & 16) >> 1);
    const int mSel = (lid >> 3) & 1;
    const int krB = lid & 15;
    const int nSel = lid >> 4;
    const int xA = krA & 7;
    const int xB = krB & 7;

    for (int s = 0; s < 8; s++) {
        if (s < 7) { asm volatile("cp.async.wait_group 1;" ::: "memory"); }
        else       { asm volatile("cp.async.wait_group 0;" ::: "memory"); }
        __syncthreads();

        if (s + 2 < 8) {
            kvp_load_sub(sbase + (uint32_t)((s + 2) % 3) * KVP_STAGE,
                         kbase, vbase, n0, s + 2, tid);
            asm volatile("cp.async.commit_group;" ::: "memory");
        }

        const uint32_t stV = sbase + (uint32_t)(s % 3) * KVP_STAGE;
        const uint32_t stK = stV + 4096;
#pragma unroll
        for (int kl = 0; kl < 2; kl++) {
            const int rowA = kl * 16 + krA;
            const int rowB = kl * 16 + krB;
            uint32_t a[4][4];
#pragma unroll
            for (int mt = 0; mt < 4; mt++) {
                uint32_t ch = (uint32_t)((mt * 2 + mSel) ^ xA) << 4;
                ldsm4t(a[mt], stV + rowA * 128 + ch);
            }
            uint32_t bf[4];
            {
                uint32_t ch = (uint32_t)((wid * 2 + nSel) ^ xB) << 4;
                ldsm4t(bf, stK + rowB * 128 + ch);
            }
#pragma unroll
            for (int mt = 0; mt < 4; mt++) {
                hmma(acc[mt][0], a[mt], &bf[0]);
                hmma(acc[mt][1], a[mt], &bf[2]);
            }
        }
    }

    float* dst = g_KVp + ((size_t)pair * 8 + split) * (HDIM * HDIM);
    const int d1c = wid * 16 + (lid & 3) * 2;
#pragma unroll
    for (int mt = 0; mt < 4; mt++) {
        const int d2r = mt * 16 + (lid >> 2);
#pragma unroll
        for (int bn = 0; bn < 2; bn++) {
            *(float2*)&dst[(size_t)d2r * HDIM + d1c + bn * 8] =
                *(float2*)&acc[mt][bn][0];
            *(float2*)&dst[(size_t)(d2r + 8) * HDIM + d1c + bn * 8] =
                *(float2*)&acc[mt][bn][2];
        }
    }
}

// ---------------------------------------------------------------------------
// kv_reduce: float4-vectorized; sum 8 splits, scale, emit fp16 hi+lo
// ---------------------------------------------------------------------------
__global__ __launch_bounds__(256)
void kv_reduce()
{
    int idx = blockIdx.x * 256 + threadIdx.x;
    int pair = idx >> 10, off = idx & 1023;
    const float4* src = (const float4*)g_KVp + (size_t)pair * 8 * 1024 + off;
    float4 s = make_float4(0.f, 0.f, 0.f, 0.f);
#pragma unroll
    for (int k = 0; k < 8; k++) {
        float4 v = src[(size_t)k * 1024];
        s.x += v.x; s.y += v.y; s.z += v.z; s.w += v.w;
    }
    s.x *= SCALE; s.y *= SCALE; s.z *= SCALE; s.w *= SCALE;

    __half hi[4], lo[4];
    hi[0] = __float2half(s.x); lo[0] = __float2half(s.x - __half2float(hi[0]));
    hi[1] = __float2half(s.y); lo[1] = __float2half(s.y - __half2float(hi[1]));
    hi[2] = __float2half(s.z); lo[2] = __float2half(s.z - __half2float(hi[2]));
    hi[3] = __float2half(s.w); lo[3] = __float2half(s.w - __half2float(hi[3]));
    *(uint2*)(g_KVThi + 4 * (size_t)idx) = *(uint2*)hi;
    *(uint2*)(g_KVTlo + 4 * (size_t)idx) = *(uint2*)lo;
}

// ---------------------------------------------------------------------------
// Kernel C: out = q @ KV via HMMA, 128-row tiles; contiguous packed q reads
// grid (64 pairs, 16 chunks of 128 rows), 256 threads
// ---------------------------------------------------------------------------
__global__ __launch_bounds__(256)
void out_gemm(float* __restrict__ out)
{
    extern __shared__ char smc[];
    const uint32_t sq  = smem_u32(smc);
    const uint32_t sbh = sq + 16384;
    const uint32_t sbl = sbh + 8192;

    const int pair = blockIdx.x;
    const int nc   = blockIdx.y;
    const int tid = threadIdx.x;
    const int wid = tid >> 5, lid = tid & 31;

    const __half* qbase = g_Ypack + ((size_t)pair * NSEQ) * HDIM;   // t=0 plane
    const int n0 = nc * 128;

#pragma unroll
    for (int i = 0; i < 4; i++) {
        int o = tid + i * 256;
        int r = o >> 3, ch = o & 7;
        uint32_t sw = r * 128 + ((ch ^ (r & 7)) << 4);
        cp16(sq + sw, qbase + (size_t)(n0 + r) * HDIM + ch * 8);
    }
    const __half* kvh = g_KVThi + (size_t)pair * 4096;
    const __half* kvl = g_KVTlo + (size_t)pair * 4096;
#pragma unroll
    for (int i = 0; i < 2; i++) {
        int o = tid + i * 256;
        int r = o >> 3, ch = o & 7;
        uint32_t sw = r * 128 + ((ch ^ (r & 7)) << 4);
        cp16(sbh + sw, kvh + r * 64 + ch * 8);
        cp16(sbl + sw, kvl + r * 64 + ch * 8);
    }
    asm volatile("cp.async.commit_group;" ::: "memory");
    asm volatile("cp.async.wait_group 0;" ::: "memory");
    __syncthreads();

    float acc[8][4];
#pragma unroll
    for (int nt = 0; nt < 8; nt++)
#pragma unroll
        for (int j = 0; j < 4; j++) acc[nt][j] = 0.0f;

    const uint32_t aRowOff = (uint32_t)(wid * 16 + (lid & 15)) * 128;
    const uint32_t bRowOff = (uint32_t)((lid & 7) + ((lid >> 4) & 1) * 8) * 128;
    const int xorC   = lid & 7;
    const int chSelA = lid >> 4;
    const int chSelB = (lid >> 3) & 1;

#pragma unroll
    for (int ks = 0; ks < 4; ks++) {
        const uint32_t chA = (uint32_t)((ks * 2 + chSelA) ^ xorC) << 4;
        const uint32_t chB = (uint32_t)((ks * 2 + chSelB) ^ xorC) << 4;
        uint32_t a[4];
        ldsm4(a, sq + aRowOff + chA);
        uint32_t bh[4][4], bl[4][4];
#pragma unroll
        for (int p = 0; p < 4; p++) {
            ldsm4(bh[p], sbh + bRowOff + p * (16 * 128) + chB);
            ldsm4(bl[p], sbl + bRowOff + p * (16 * 128) + chB);
        }
#pragma unroll
        for (int p = 0; p < 4; p++) {
            hmma(acc[2 * p + 0], a, &bh[p][0]);
            hmma(acc[2 * p + 1], a, &bh[p][2]);
            hmma(acc[2 * p + 0], a, &bl[p][0]);
            hmma(acc[2 * p + 1], a, &bl[p][2]);
        }
    }

    float* obase = out + ((size_t)pair * NSEQ + (size_t)n0) * HDIM;
    const int r0 = wid * 16 + (lid >> 2);
    const int ec = (lid & 3) * 2;
#pragma unroll
    for (int nt = 0; nt < 8; nt++) {
        *(float2*)&obase[(size_t)r0 * HDIM + ec + nt * 8] = *(float2*)&acc[nt][0];
        *(float2*)&obase[(size_t)(r0 + 8) * HDIM + ec + nt * 8] = *(float2*)&acc[nt][2];
    }
}

// ---------------------------------------------------------------------------
// Host launch (round-12 sequential schedule, 6 kernels)
// ---------------------------------------------------------------------------
extern "C" void kernel_launch(void* const* d_in, const int* in_sizes, int n_in,
                              void* d_out, int out_size)
{
    (void)in_sizes; (void)n_in; (void)out_size;
    const float* x    = (const float*)d_in[0];
    const float* W    = (const float*)d_in[1];
    const float* bias = (const float*)d_in[2];
    float* out = (float*)d_out;

    static int attr_set = 0;
    if (!attr_set) {
        cudaFuncSetAttribute(qkv_mma, cudaFuncAttributeMaxDynamicSharedMemorySize, SMEM_DYN);
        cudaFuncSetAttribute(kv_partial, cudaFuncAttributeMaxDynamicSharedMemorySize, KVP_SMEM);
        cudaFuncSetAttribute(out_gemm, cudaFuncAttributeMaxDynamicSharedMemorySize, OUT_SMEM);
        attr_set = 1;
    }

    conv_x<<<(M_ROWS * K_DIM / 4) / 256, 256>>>((const float4*)x);
    conv_w<<<dim3(16, 32), 256>>>(W, bias);

    qkv_mma<<<dim3(N_COLS / QBN, M_ROWS / QBM), 256, SMEM_DYN>>>();

    kv_partial<<<dim3(64, 8), 128, KVP_SMEM>>>();
    kv_reduce<<<256, 256>>>();
    out_gemm<<<dim3(64, 16), 256, OUT_SMEM>>>(out);
}